// round 16
// baseline (speedup 1.0000x reference)
#include <cuda_runtime.h>
#include <cuda_bf16.h>
#include <cstdint>

#define N_NODES 100000
#define N_EDGES 3200000
#define N_GRAPHS 512
#define IN_CH 50
#define HID 256
#define KDIM 100
#define FT_STRIDE 100032      // padded featT row (floats); 16B-divisible
#define TILE_N 64             // nodes per block in node_mm
#define KC 10                 // k-rows per pipeline chunk
#define NCHUNK 10             // KDIM / KC
#define SF_ROW 68             // sF row stride (floats) = 17 x 16B
#define SW_BYTES (KC * HID * 4)      // 10240
#define NBLK_SCAN 391                // ceil(100000/256)

// ---------------- device scratch ----------------
__device__ __align__(16) float g_featT[KDIM * FT_STRIDE];   // K-major features (40MB)
__device__ __align__(16) float g_Wt[KDIM * HID];            // K-major weights
__device__ __align__(16) uint32_t g_xbf[N_NODES * 25];      // x as bf16x2 pairs (10MB)
__device__ __align__(16) float g_pooled[N_GRAPHS * HID];
__device__ __align__(16) float g_gcnt[N_GRAPHS];
__device__ __align__(16) int   g_ptr[N_NODES + 1];          // CSR row pointers
__device__ __align__(16) int   g_cur[N_NODES];              // scatter cursors
__device__ __align__(16) int   g_csr[N_EDGES];              // src sorted by dst
__device__ int g_bsum[NBLK_SCAN];
__device__ int g_bscan[NBLK_SCAN];

// ---------------- f32x2 / cp.async helpers ----------------
__device__ __forceinline__ unsigned long long pack2(float lo, float hi) {
    unsigned long long r;
    asm("mov.b64 %0, {%1, %2};" : "=l"(r) : "f"(lo), "f"(hi));
    return r;
}
__device__ __forceinline__ void unpack2(unsigned long long v, float& lo, float& hi) {
    asm("mov.b64 {%0, %1}, %2;" : "=f"(lo), "=f"(hi) : "l"(v));
}
__device__ __forceinline__ void ffma2(unsigned long long& d,
                                      unsigned long long a, unsigned long long b) {
    asm("fma.rn.f32x2 %0, %1, %2, %0;" : "+l"(d) : "l"(a), "l"(b));
}
__device__ __forceinline__ uint32_t smem_u32(const void* p) {
    uint32_t a;
    asm("{ .reg .u64 t; cvta.to.shared.u64 t, %1; cvt.u32.u64 %0, t; }"
        : "=r"(a) : "l"(p));
    return a;
}
__device__ __forceinline__ void cp16(uint32_t dst, const void* src) {
    asm volatile("cp.async.ca.shared.global [%0], [%1], 16;"
                 :: "r"(dst), "l"(src) : "memory");
}
#define CP_COMMIT() asm volatile("cp.async.commit_group;" ::: "memory")
#define CP_WAIT1()  asm volatile("cp.async.wait_group 1;" ::: "memory")
#define CP_WAIT0()  asm volatile("cp.async.wait_group 0;" ::: "memory")

// ---------------- kernel: zero hist + pooled ----------------
__global__ __launch_bounds__(256) void zero_misc()
{
    int i = blockIdx.x * blockDim.x + threadIdx.x;
    int stride = gridDim.x * blockDim.x;
    for (; i <= N_NODES; i += stride) g_ptr[i] = 0;
    for (i = blockIdx.x * blockDim.x + threadIdx.x; i < N_GRAPHS * HID; i += stride)
        g_pooled[i] = 0.f;
    for (i = blockIdx.x * blockDim.x + threadIdx.x; i < N_GRAPHS; i += stride)
        g_gcnt[i] = 0.f;
}

// ---------------- kernel: x -> packed bf16x2 (for agg gather) ----------
__global__ __launch_bounds__(256) void x_to_bf16(const float* __restrict__ x)
{
    int i = blockIdx.x * 256 + threadIdx.x;
    int stride = gridDim.x * 256;
    const float2* x2 = (const float2*)x;
    for (; i < N_NODES * 25; i += stride) {
        float2 v = x2[i];
        __nv_bfloat162 b = __float22bfloat162_rn(v);
        g_xbf[i] = *(uint32_t*)&b;
    }
}

// ---------------- kernel: build K-major weight matrix ----------------
__global__ __launch_bounds__(256) void build_wt(
    const float* __restrict__ W_l, const float* __restrict__ W_r)
{
    int i = blockIdx.x * 256 + threadIdx.x;
    if (i < KDIM * HID) {
        int k = i / HID, c = i - k * HID;
        g_Wt[i] = (k < IN_CH) ? W_r[c * IN_CH + k] : W_l[c * IN_CH + k - IN_CH];
    }
}

// ---------------- kernel: transpose x -> featT rows [0,50) ----------------
__global__ __launch_bounds__(256) void transpose_x(const float* __restrict__ x)
{
    __shared__ float t[32][33];
    int n0 = blockIdx.x * 32, k0 = blockIdx.y * 32;
    int tx = threadIdx.x, ty = threadIdx.y;
    #pragma unroll
    for (int i = 0; i < 4; i++) {
        int r = ty + 8 * i;
        int k = k0 + tx;
        t[r][tx] = (k < IN_CH) ? x[(n0 + r) * IN_CH + k] : 0.f;
    }
    __syncthreads();
    #pragma unroll
    for (int i = 0; i < 4; i++) {
        int r = ty + 8 * i;
        int k = k0 + r;
        if (k < IN_CH) g_featT[k * FT_STRIDE + n0 + tx] = t[tx][r];
    }
}

// ---------------- CSR build: histogram of dst ----------------
__global__ __launch_bounds__(256) void hist(const int* __restrict__ ei)
{
    int i = blockIdx.x * 256 + threadIdx.x;
    if (i < N_EDGES) atomicAdd(&g_ptr[ei[N_EDGES + i]], 1);
}

// ---------------- CSR build: 3-step exclusive scan of g_ptr[0..N) ---------
__global__ __launch_bounds__(256) void scan_blocks()
{
    __shared__ int s[256];
    int t = threadIdx.x;
    int i = blockIdx.x * 256 + t;
    int v = (i < N_NODES) ? g_ptr[i] : 0;
    s[t] = v;
    __syncthreads();
    for (int o = 1; o < 256; o <<= 1) {
        int u = (t >= o) ? s[t - o] : 0;
        __syncthreads();
        s[t] += u;
        __syncthreads();
    }
    if (i < N_NODES) g_ptr[i] = s[t] - v;        // block-local exclusive
    if (t == 255) g_bsum[blockIdx.x] = s[255];
}
__global__ __launch_bounds__(512) void scan_top()
{
    __shared__ int s[512];
    int t = threadIdx.x;
    int v = (t < NBLK_SCAN) ? g_bsum[t] : 0;
    s[t] = v;
    __syncthreads();
    for (int o = 1; o < 512; o <<= 1) {
        int u = (t >= o) ? s[t - o] : 0;
        __syncthreads();
        s[t] += u;
        __syncthreads();
    }
    if (t < NBLK_SCAN) g_bscan[t] = s[t] - v;    // exclusive
}
__global__ __launch_bounds__(256) void scan_add()
{
    int i = blockIdx.x * 256 + threadIdx.x;
    if (i < N_NODES) {
        int p = g_ptr[i] + g_bscan[blockIdx.x];
        g_ptr[i] = p;
        g_cur[i] = p;
    }
    if (i == 0) g_ptr[N_NODES] = N_EDGES;
}

// ---------------- CSR build: scatter src by dst ----------------
__global__ __launch_bounds__(256) void scatter_csr(const int* __restrict__ ei)
{
    int i = blockIdx.x * 256 + threadIdx.x;
    if (i < N_EDGES) {
        int s = ei[i];
        int d = ei[N_EDGES + i];
        int pos = atomicAdd(&g_cur[d], 1);
        g_csr[pos] = s;
    }
}

// ---------------- aggregate: warp per node, bf16 gather, K-major out ------
// Lane owns one channel pair; src row is 25 bf16x2 words (100B, halved L2
// traffic vs f32). Accumulate fp32; mean folded; smem transpose flush.
__global__ __launch_bounds__(256) void agg_csr()
{
    __shared__ float sT[IN_CH][9];
    int w = threadIdx.x >> 5, lane = threadIdx.x & 31;
    int node = blockIdx.x * 8 + w;       // 12500*8 == N_NODES exactly
    int beg = g_ptr[node], end = g_ptr[node + 1];
    float2 acc = make_float2(0.f, 0.f);
    for (int e = beg; e < end; e += 32) {
        int r = e + lane;
        int sv = (r < end) ? g_csr[r] : 0;
        int m = min(32, end - e);
        for (int i = 0; i < m; i++) {
            int si = __shfl_sync(0xffffffffu, sv, i);
            if (lane < 25) {
                uint32_t v = g_xbf[si * 25 + lane];
                acc.x += __uint_as_float(v << 16);          // low bf16
                acc.y += __uint_as_float(v & 0xffff0000u);  // high bf16
            }
        }
    }
    float inv = 1.0f / fmaxf((float)(end - beg), 1.0f);
    if (lane < 25) {
        sT[lane * 2][w]     = acc.x * inv;
        sT[lane * 2 + 1][w] = acc.y * inv;
    }
    __syncthreads();
    int n0 = blockIdx.x * 8;
    for (int t = threadIdx.x; t < IN_CH * 8; t += 256) {
        int k = t >> 3, j = t & 7;
        g_featT[(IN_CH + k) * FT_STRIDE + n0 + j] = sT[k][j];
    }
}

// ---------------- kernel: nodes per graph (atomic-free) ------------------
__global__ __launch_bounds__(256) void count_nodes(const int* __restrict__ batch)
{
    int i = blockIdx.x * blockDim.x + threadIdx.x;
    if (i >= N_NODES) return;
    int g = batch[i];
    if (i == 0 || batch[i - 1] != g) {
        int j = i + 1;
        while (j < N_NODES && batch[j] == g) j++;
        g_gcnt[g] = (float)(j - i);
    }
}

// ---------------- node GEMM, cp.async double-buffered (R12-best) ----------
__global__ __launch_bounds__(512, 2) void node_mm(
    const int* __restrict__ batch, const float* __restrict__ b_l)
{
    __shared__ float sW[2][KC * HID];
    __shared__ float sF[2][KC * SF_ROW];
    __shared__ int   sGid[TILE_N];

    int tid = threadIdx.x;
    int n0  = blockIdx.x * TILE_N;

    if (tid < TILE_N) {
        int node = n0 + tid;
        sGid[tid] = (node < N_NODES) ? batch[node] : -1;
    }

    uint32_t swb[2] = {smem_u32(sW[0]), smem_u32(sW[1])};
    uint32_t sfb[2] = {smem_u32(sF[0]), smem_u32(sF[1])};

    auto stage = [&](int kc, int b) {
        const char* wsrc = (const char*)g_Wt + kc * SW_BYTES;
        #pragma unroll
        for (int i = tid; i < SW_BYTES / 16; i += 512)
            cp16(swb[b] + i * 16, wsrc + i * 16);
        if (tid < KC * 16) {
            int r = tid >> 4, c16 = tid & 15;
            cp16(sfb[b] + r * (SF_ROW * 4) + c16 * 16,
                 (const char*)(g_featT + (kc * KC + r) * FT_STRIDE + n0) + c16 * 16);
        }
    };

    int tc = tid & 63;
    int tn = tid >> 6;

    unsigned long long acc[4][4];
    #pragma unroll
    for (int a = 0; a < 4; a++)
        #pragma unroll
        for (int p = 0; p < 4; p++) acc[a][p] = 0ull;

    stage(0, 0);
    CP_COMMIT();

    for (int c = 0; c < NCHUNK; c++) {
        int b = c & 1;
        if (c + 1 < NCHUNK) {
            stage(c + 1, (c + 1) & 1);
            CP_COMMIT();
            CP_WAIT1();
        } else {
            CP_WAIT0();
        }
        __syncthreads();

        const float4* sW4 = (const float4*)sW[b];
        const ulonglong2* sFu = (const ulonglong2*)sF[b];
        #pragma unroll
        for (int kk = 0; kk < KC; kk++) {
            float4 w = sW4[kk * 64 + tc];
            ulonglong2 fA = sFu[kk * 17 + tn * 2];
            ulonglong2 fB = sFu[kk * 17 + tn * 2 + 1];
            unsigned long long wb2[4];
            wb2[0] = pack2(w.x, w.x);
            wb2[1] = pack2(w.y, w.y);
            wb2[2] = pack2(w.z, w.z);
            wb2[3] = pack2(w.w, w.w);
            unsigned long long fp[4] = {fA.x, fA.y, fB.x, fB.y};
            #pragma unroll
            for (int a = 0; a < 4; a++)
                #pragma unroll
                for (int p = 0; p < 4; p++)
                    ffma2(acc[a][p], wb2[a], fp[p]);
        }
        __syncthreads();
    }

    float h[4][8];
    #pragma unroll
    for (int a = 0; a < 4; a++)
        #pragma unroll
        for (int p = 0; p < 4; p++)
            unpack2(acc[a][p], h[a][2 * p], h[a][2 * p + 1]);

    float4 bq = ((const float4*)b_l)[tc];
    float bias[4] = {bq.x, bq.y, bq.z, bq.w};

    float run[4];
    #pragma unroll
    for (int a = 0; a < 4; a++) run[a] = 0.0f;
    int runG = sGid[tn * 8];

    #pragma unroll
    for (int j = 0; j < 8; j++) {
        int g = sGid[tn * 8 + j];
        if (g != runG) {
            if (runG >= 0) {
                #pragma unroll
                for (int a = 0; a < 4; a++)
                    atomicAdd(&g_pooled[runG * HID + tc * 4 + a], run[a]);
            }
            #pragma unroll
            for (int a = 0; a < 4; a++) run[a] = 0.0f;
            runG = g;
        }
        if (g >= 0) {
            #pragma unroll
            for (int a = 0; a < 4; a++) {
                float v = h[a][j] + bias[a];
                v = v > 0.f ? v : 0.01f * v;
                run[a] += v;
            }
        }
    }
    if (runG >= 0) {
        #pragma unroll
        for (int a = 0; a < 4; a++)
            atomicAdd(&g_pooled[runG * HID + tc * 4 + a], run[a]);
    }
}

// ---------------- pooled mean + classifier ----------------
__global__ __launch_bounds__(256) void finalize(
    const float* __restrict__ W_c, const float* __restrict__ b_c,
    float* __restrict__ out)
{
    int g = blockIdx.x;
    int t = threadIdx.x;
    float inv = 1.0f / fmaxf(g_gcnt[g], 1.0f);
    float p = g_pooled[g * HID + t] * inv;
    float s0 = p * W_c[t];
    float s1 = p * W_c[HID + t];
    #pragma unroll
    for (int off = 16; off > 0; off >>= 1) {
        s0 += __shfl_down_sync(0xffffffffu, s0, off);
        s1 += __shfl_down_sync(0xffffffffu, s1, off);
    }
    __shared__ float sh0[8], sh1[8];
    int lane = t & 31, wid = t >> 5;
    if (lane == 0) { sh0[wid] = s0; sh1[wid] = s1; }
    __syncthreads();
    if (t == 0) {
        float t0 = b_c[0], t1 = b_c[1];
        #pragma unroll
        for (int w = 0; w < 8; w++) { t0 += sh0[w]; t1 += sh1[w]; }
        out[g * 2 + 0] = t0;
        out[g * 2 + 1] = t1;
    }
}

// ---------------- launch: kernel launches ONLY ----------------
extern "C" void kernel_launch(void* const* d_in, const int* in_sizes, int n_in,
                              void* d_out, int out_size)
{
    const float* x     = (const float*)d_in[0];
    const int*   ei    = (const int*)d_in[1];    // int32 (JAX x64 disabled)
    const int*   batch = (const int*)d_in[2];    // int32
    const float* W_l   = (const float*)d_in[3];
    const float* b_l   = (const float*)d_in[4];
    const float* W_r   = (const float*)d_in[5];
    const float* W_c   = (const float*)d_in[6];
    const float* b_c   = (const float*)d_in[7];
    float*       out   = (float*)d_out;

    dim3 tgrid(N_NODES / 32, 2), tblk(32, 8);
    int eb = (N_EDGES + 255) / 256;

    zero_misc<<<296, 256>>>();
    x_to_bf16<<<592, 256>>>(x);
    build_wt<<<(KDIM * HID + 255) / 256, 256>>>(W_l, W_r);
    transpose_x<<<tgrid, tblk>>>(x);
    hist<<<eb, 256>>>(ei);
    scan_blocks<<<NBLK_SCAN, 256>>>();
    scan_top<<<1, 512>>>();
    scan_add<<<NBLK_SCAN, 256>>>();
    scatter_csr<<<eb, 256>>>(ei);
    agg_csr<<<N_NODES / 8, 256>>>();
    count_nodes<<<(N_NODES + 255) / 256, 256>>>(batch);
    node_mm<<<(N_NODES + TILE_N - 1) / TILE_N, 512>>>(batch, b_l);
    finalize<<<N_GRAPHS, 256>>>(W_c, b_c, out);
}

// round 17
// speedup vs baseline: 1.2978x; 1.2978x over previous
#include <cuda_runtime.h>
#include <cstdint>

#define N_NODES 100000
#define N_EDGES 3200000
#define N_GRAPHS 512
#define IN_CH 50
#define HID 256
#define KPAD 104              // K padded to 13 mma k-steps of 8
#define NKS 13
#define FT_STRIDE 100096      // padded featT row (floats); >= 782*128, 16B-div
#define TILE_N 128            // nodes per CTA in node_mm
#define SB_STRIDE 136         // sB row stride (floats): 8k+c bank-exact
#define NBLK_SCAN 391         // ceil(100000/256)

// ---------------- device scratch ----------------
__device__ __align__(16) float g_featT[KPAD * FT_STRIDE];   // K-major features
__device__ __align__(16) float g_WtF[NKS * 16 * 128];       // weights, frag order
__device__ __align__(16) float g_pooled[N_GRAPHS * HID];
__device__ __align__(16) float g_gcnt[N_GRAPHS];
__device__ __align__(16) int   g_ptr[N_NODES + 1];          // CSR row pointers
__device__ __align__(16) int   g_cur[N_NODES];              // scatter cursors
__device__ __align__(16) int   g_csr[N_EDGES];              // src sorted by dst
__device__ int g_bsum[NBLK_SCAN];
__device__ int g_bscan[NBLK_SCAN];

// ---------------- helpers ----------------
__device__ __forceinline__ uint32_t smem_u32(const void* p) {
    uint32_t a;
    asm("{ .reg .u64 t; cvta.to.shared.u64 t, %1; cvt.u32.u64 %0, t; }"
        : "=r"(a) : "l"(p));
    return a;
}
__device__ __forceinline__ void cp16(uint32_t dst, const void* src) {
    asm volatile("cp.async.ca.shared.global [%0], [%1], 16;"
                 :: "r"(dst), "l"(src) : "memory");
}
#define CP_COMMIT() asm volatile("cp.async.commit_group;" ::: "memory")
#define CP_WAIT1()  asm volatile("cp.async.wait_group 1;" ::: "memory")
#define CP_WAIT0()  asm volatile("cp.async.wait_group 0;" ::: "memory")

__device__ __forceinline__ float to_tf32(float v) {
    uint32_t o;
    asm("cvt.rna.tf32.f32 %0, %1;" : "=r"(o) : "f"(v));
    return __uint_as_float(o);
}
__device__ __forceinline__ void mma_tf32(float* c,
    uint32_t a0, uint32_t a1, uint32_t a2, uint32_t a3,
    uint32_t b0, uint32_t b1)
{
    asm volatile(
        "mma.sync.aligned.m16n8k8.row.col.f32.tf32.tf32.f32 "
        "{%0,%1,%2,%3}, {%4,%5,%6,%7}, {%8,%9}, {%0,%1,%2,%3};"
        : "+f"(c[0]), "+f"(c[1]), "+f"(c[2]), "+f"(c[3])
        : "r"(a0), "r"(a1), "r"(a2), "r"(a3), "r"(b0), "r"(b1));
}

// ---------------- kernel: zero ptr/pooled + featT pad rows ----------------
__global__ __launch_bounds__(256) void zero_misc()
{
    int i = blockIdx.x * blockDim.x + threadIdx.x;
    int stride = gridDim.x * blockDim.x;
    for (; i <= N_NODES; i += stride) g_ptr[i] = 0;
    for (i = blockIdx.x * blockDim.x + threadIdx.x; i < N_GRAPHS * HID; i += stride)
        g_pooled[i] = 0.f;
    for (i = blockIdx.x * blockDim.x + threadIdx.x; i < N_GRAPHS; i += stride)
        g_gcnt[i] = 0.f;
    // zero featT k-pad rows 100..103
    for (i = blockIdx.x * blockDim.x + threadIdx.x; i < 4 * FT_STRIDE; i += stride)
        g_featT[100 * FT_STRIDE + i] = 0.f;
}

// ---------------- kernel: weights -> mma fragment order (tf32) ------------
// g_WtF[((ks*16 + mt)*32 + lane)*4 + r]:
//   ch = mt*16 + lane/4 + (r&1)*8 ;  k = ks*8 + lane%4 + (r>>1)*4
__global__ __launch_bounds__(256) void build_wtf(
    const float* __restrict__ W_l, const float* __restrict__ W_r)
{
    int i = blockIdx.x * 256 + threadIdx.x;
    if (i >= NKS * 2048) return;
    int ks   = i >> 11;
    int rem  = i & 2047;
    int mt   = rem >> 7;
    int q    = rem & 127;
    int lane = q >> 2, r = q & 3;
    int ch = mt * 16 + (lane >> 2) + (r & 1) * 8;
    int k  = ks * 8 + (lane & 3) + (r >> 1) * 4;
    float v = 0.f;
    if (k < IN_CH)          v = W_r[ch * IN_CH + k];
    else if (k < 2 * IN_CH) v = W_l[ch * IN_CH + k - IN_CH];
    g_WtF[i] = to_tf32(v);
}

// ---------------- kernel: transpose x -> featT rows [0,50), tf32 ----------
__global__ __launch_bounds__(256) void transpose_x(const float* __restrict__ x)
{
    __shared__ float t[32][33];
    int n0 = blockIdx.x * 32, k0 = blockIdx.y * 32;
    int tx = threadIdx.x, ty = threadIdx.y;
    #pragma unroll
    for (int i = 0; i < 4; i++) {
        int r = ty + 8 * i;
        int k = k0 + tx;
        t[r][tx] = (k < IN_CH) ? x[(n0 + r) * IN_CH + k] : 0.f;
    }
    __syncthreads();
    #pragma unroll
    for (int i = 0; i < 4; i++) {
        int r = ty + 8 * i;
        int k = k0 + r;
        if (k < IN_CH) g_featT[k * FT_STRIDE + n0 + tx] = to_tf32(t[tx][r]);
    }
}

// ---------------- CSR build: histogram of dst ----------------
__global__ __launch_bounds__(256) void hist(const int* __restrict__ ei)
{
    int i = blockIdx.x * 256 + threadIdx.x;
    if (i < N_EDGES) atomicAdd(&g_ptr[ei[N_EDGES + i]], 1);
}

// ---------------- CSR build: 3-step exclusive scan ----------------
__global__ __launch_bounds__(256) void scan_blocks()
{
    __shared__ int s[256];
    int t = threadIdx.x;
    int i = blockIdx.x * 256 + t;
    int v = (i < N_NODES) ? g_ptr[i] : 0;
    s[t] = v;
    __syncthreads();
    for (int o = 1; o < 256; o <<= 1) {
        int u = (t >= o) ? s[t - o] : 0;
        __syncthreads();
        s[t] += u;
        __syncthreads();
    }
    if (i < N_NODES) g_ptr[i] = s[t] - v;
    if (t == 255) g_bsum[blockIdx.x] = s[255];
}
__global__ __launch_bounds__(512) void scan_top()
{
    __shared__ int s[512];
    int t = threadIdx.x;
    int v = (t < NBLK_SCAN) ? g_bsum[t] : 0;
    s[t] = v;
    __syncthreads();
    for (int o = 1; o < 512; o <<= 1) {
        int u = (t >= o) ? s[t - o] : 0;
        __syncthreads();
        s[t] += u;
        __syncthreads();
    }
    if (t < NBLK_SCAN) g_bscan[t] = s[t] - v;
}
__global__ __launch_bounds__(256) void scan_add()
{
    int i = blockIdx.x * 256 + threadIdx.x;
    if (i < N_NODES) {
        int p = g_ptr[i] + g_bscan[blockIdx.x];
        g_ptr[i] = p;
        g_cur[i] = p;
    }
    if (i == 0) g_ptr[N_NODES] = N_EDGES;
}

// ---------------- CSR build: scatter src by dst ----------------
__global__ __launch_bounds__(256) void scatter_csr(const int* __restrict__ ei)
{
    int i = blockIdx.x * 256 + threadIdx.x;
    if (i < N_EDGES) {
        int s = ei[i];
        int d = ei[N_EDGES + i];
        int pos = atomicAdd(&g_cur[d], 1);
        g_csr[pos] = s;
    }
}

// ---------------- aggregate: warp per node, f32 gather, tf32 K-major out --
__global__ __launch_bounds__(256) void agg_csr(const float* __restrict__ x)
{
    __shared__ float sT[IN_CH][9];
    int w = threadIdx.x >> 5, lane = threadIdx.x & 31;
    int node = blockIdx.x * 8 + w;       // 12500*8 == N_NODES exactly
    int beg = g_ptr[node], end = g_ptr[node + 1];
    const float2* x2 = (const float2*)x;
    float2 acc = make_float2(0.f, 0.f);
    for (int e = beg; e < end; e += 32) {
        int r = e + lane;
        int sv = (r < end) ? g_csr[r] : 0;
        int m = min(32, end - e);
        for (int i = 0; i < m; i++) {
            int si = __shfl_sync(0xffffffffu, sv, i);
            if (lane < 25) {
                float2 v = x2[si * 25 + lane];
                acc.x += v.x;
                acc.y += v.y;
            }
        }
    }
    float inv = 1.0f / fmaxf((float)(end - beg), 1.0f);
    if (lane < 25) {
        sT[lane * 2][w]     = acc.x * inv;
        sT[lane * 2 + 1][w] = acc.y * inv;
    }
    __syncthreads();
    int n0 = blockIdx.x * 8;
    for (int t = threadIdx.x; t < IN_CH * 8; t += 256) {
        int k = t >> 3, j = t & 7;
        g_featT[(IN_CH + k) * FT_STRIDE + n0 + j] = to_tf32(sT[k][j]);
    }
}

// ---------------- nodes per graph (atomic-free) ----------------
__global__ __launch_bounds__(256) void count_nodes(const int* __restrict__ batch)
{
    int i = blockIdx.x * blockDim.x + threadIdx.x;
    if (i >= N_NODES) return;
    int g = batch[i];
    if (i == 0 || batch[i - 1] != g) {
        int j = i + 1;
        while (j < N_NODES && batch[j] == g) j++;
        g_gcnt[g] = (float)(j - i);
    }
}

// ---------------- node GEMM via mma.sync tf32 + fused epilogue ------------
// CTA: 256 ch x 128 nodes, 512 thr = 16 warps (8 M-groups x 2 N-groups).
// Warp: 32ch x 64n = 2 m-frags x 8 n-frags, 13 k-steps. A staged in frag
// order (LDS.128), B = featT rows (LDS.32, conflict-free stride 136).
__global__ __launch_bounds__(512, 1) void node_mm(
    const int* __restrict__ batch, const float* __restrict__ b_l)
{
    __shared__ float sA[2][2048];            // 16 mt x 32 lanes x 4 regs
    __shared__ float sB[2][8 * SB_STRIDE];   // 8 k-rows x 136
    __shared__ int   sGid[TILE_N];
    __shared__ float sBias[HID];

    int tid  = threadIdx.x;
    int wid  = tid >> 5, lane = tid & 31;
    int wm   = wid & 7, wn = wid >> 3;
    int n0   = blockIdx.x * TILE_N;

    if (tid < TILE_N) {
        int node = n0 + tid;
        sGid[tid] = (node < N_NODES) ? batch[node] : -1;
    }
    if (tid < HID) sBias[tid] = b_l[tid];

    uint32_t sab[2] = {smem_u32(sA[0]), smem_u32(sA[1])};
    uint32_t sbb[2] = {smem_u32(sB[0]), smem_u32(sB[1])};

    auto stage = [&](int ks, int b) {
        cp16(sab[b] + tid * 16, (const char*)(g_WtF + ks * 2048) + tid * 16);
        if (tid < 256) {
            int r = tid >> 5, s = tid & 31;
            cp16(sbb[b] + (r * SB_STRIDE + s * 4) * 4,
                 (const char*)(g_featT + (ks * 8 + r) * FT_STRIDE + n0) + s * 16);
        }
    };

    float acc[2][8][4];
    #pragma unroll
    for (int mt = 0; mt < 2; mt++)
        #pragma unroll
        for (int nt = 0; nt < 8; nt++)
            #pragma unroll
            for (int r = 0; r < 4; r++) acc[mt][nt][r] = 0.f;

    stage(0, 0);
    CP_COMMIT();

    for (int ks = 0; ks < NKS; ks++) {
        int b = ks & 1;
        if (ks + 1 < NKS) {
            stage(ks + 1, b ^ 1);
            CP_COMMIT();
            CP_WAIT1();
        } else {
            CP_WAIT0();
        }
        __syncthreads();

        uint32_t a[2][4];
        #pragma unroll
        for (int mt = 0; mt < 2; mt++) {
            float4 av = *(const float4*)(sA[b] + (wm * 2 + mt) * 128 + lane * 4);
            a[mt][0] = __float_as_uint(av.x);
            a[mt][1] = __float_as_uint(av.y);
            a[mt][2] = __float_as_uint(av.z);
            a[mt][3] = __float_as_uint(av.w);
        }
        #pragma unroll
        for (int nt = 0; nt < 8; nt++) {
            int col = wn * 64 + nt * 8 + (lane >> 2);
            uint32_t b0 = __float_as_uint(sB[b][(lane & 3) * SB_STRIDE + col]);
            uint32_t b1 = __float_as_uint(sB[b][((lane & 3) + 4) * SB_STRIDE + col]);
            mma_tf32(acc[0][nt], a[0][0], a[0][1], a[0][2], a[0][3], b0, b1);
            mma_tf32(acc[1][nt], a[1][0], a[1][1], a[1][2], a[1][3], b0, b1);
        }
        __syncthreads();
    }

    // epilogue: bias + leakyReLU + run-merged pooling REDs (batch sorted).
    // lane owns ch: wm*32 + mt*16 + lane/4 + h*8 ; cols: wn*64 + nt*8 + (lane%4)*2 + j
    int chb = wm * 32 + (lane >> 2);
    float bias[2][2];
    #pragma unroll
    for (int mt = 0; mt < 2; mt++)
        #pragma unroll
        for (int h = 0; h < 2; h++)
            bias[mt][h] = sBias[chb + mt * 16 + h * 8];

    float run[4] = {0.f, 0.f, 0.f, 0.f};
    int runG = sGid[wn * 64 + (lane & 3) * 2];

    #pragma unroll
    for (int nt = 0; nt < 8; nt++) {
        #pragma unroll
        for (int j = 0; j < 2; j++) {
            int col = wn * 64 + nt * 8 + (lane & 3) * 2 + j;
            int g = sGid[col];
            if (g != runG) {
                if (runG >= 0) {
                    #pragma unroll
                    for (int mt = 0; mt < 2; mt++)
                        #pragma unroll
                        for (int h = 0; h < 2; h++)
                            atomicAdd(&g_pooled[runG * HID + chb + mt * 16 + h * 8],
                                      run[mt * 2 + h]);
                }
                #pragma unroll
                for (int q = 0; q < 4; q++) run[q] = 0.f;
                runG = g;
            }
            if (g >= 0) {
                #pragma unroll
                for (int mt = 0; mt < 2; mt++)
                    #pragma unroll
                    for (int h = 0; h < 2; h++) {
                        float v = acc[mt][nt][h * 2 + j] + bias[mt][h];
                        v = v > 0.f ? v : 0.01f * v;
                        run[mt * 2 + h] += v;
                    }
            }
        }
    }
    if (runG >= 0) {
        #pragma unroll
        for (int mt = 0; mt < 2; mt++)
            #pragma unroll
            for (int h = 0; h < 2; h++)
                atomicAdd(&g_pooled[runG * HID + chb + mt * 16 + h * 8],
                          run[mt * 2 + h]);
    }
}

// ---------------- pooled mean + classifier ----------------
__global__ __launch_bounds__(256) void finalize(
    const float* __restrict__ W_c, const float* __restrict__ b_c,
    float* __restrict__ out)
{
    int g = blockIdx.x;
    int t = threadIdx.x;
    float inv = 1.0f / fmaxf(g_gcnt[g], 1.0f);
    float p = g_pooled[g * HID + t] * inv;
    float s0 = p * W_c[t];
    float s1 = p * W_c[HID + t];
    #pragma unroll
    for (int off = 16; off > 0; off >>= 1) {
        s0 += __shfl_down_sync(0xffffffffu, s0, off);
        s1 += __shfl_down_sync(0xffffffffu, s1, off);
    }
    __shared__ float sh0[8], sh1[8];
    int lane = t & 31, wid = t >> 5;
    if (lane == 0) { sh0[wid] = s0; sh1[wid] = s1; }
    __syncthreads();
    if (t == 0) {
        float t0 = b_c[0], t1 = b_c[1];
        #pragma unroll
        for (int w = 0; w < 8; w++) { t0 += sh0[w]; t1 += sh1[w]; }
        out[g * 2 + 0] = t0;
        out[g * 2 + 1] = t1;
    }
}

// ---------------- launch: kernel launches ONLY ----------------
extern "C" void kernel_launch(void* const* d_in, const int* in_sizes, int n_in,
                              void* d_out, int out_size)
{
    const float* x     = (const float*)d_in[0];
    const int*   ei    = (const int*)d_in[1];    // int32 (JAX x64 disabled)
    const int*   batch = (const int*)d_in[2];    // int32
    const float* W_l   = (const float*)d_in[3];
    const float* b_l   = (const float*)d_in[4];
    const float* W_r   = (const float*)d_in[5];
    const float* W_c   = (const float*)d_in[6];
    const float* b_c   = (const float*)d_in[7];
    float*       out   = (float*)d_out;

    dim3 tgrid(N_NODES / 32, 2), tblk(32, 8);
    int eb = (N_EDGES + 255) / 256;

    zero_misc<<<592, 256>>>();
    build_wtf<<<(NKS * 2048 + 255) / 256, 256>>>(W_l, W_r);
    transpose_x<<<tgrid, tblk>>>(x);
    hist<<<eb, 256>>>(ei);
    scan_blocks<<<NBLK_SCAN, 256>>>();
    scan_top<<<1, 512>>>();
    scan_add<<<NBLK_SCAN, 256>>>();
    scatter_csr<<<eb, 256>>>(ei);
    agg_csr<<<N_NODES / 8, 256>>>(x);
    count_nodes<<<(N_NODES + 255) / 256, 256>>>(batch);
    node_mm<<<(N_NODES + TILE_N - 1) / TILE_N, 512>>>(batch, b_l);
    finalize<<<N_GRAPHS, 256>>>(W_c, b_c, out);
}